// round 8
// baseline (speedup 1.0000x reference)
#include <cuda_runtime.h>
#include <cuda_bf16.h>
#include <cstdint>

// EdgeBlock: out[e,:] = W @ concat(edges[e], nodes[recv[e]], nodes[send[e]]) + b
// E=500000, NODE_D=EDGE_D=128, IN_D=384, W [128,384] row-major, out [E,128] f32.
// mma.sync m16n8k16 bf16, 3-pass hi/lo split (validated rel_err 4.6e-6).
// R8: W delivered as pre-packed mma B-fragments via LDG (no W smem traffic),
//     X-only double-buffered smem, 2 CTAs/SM.

#define IN_D    384
#define OUT_D   128
#define TM      128
#define KC      64
#define NCHUNK  6
#define NK16    24             // 384/16
#define THREADS 256
#define STR2    144            // bytes per X smem row (64 bf16 + 8 pad)

// smem: two buffers of (XHI,XLO) + bias
#define XHI(b)   ((b) * 36864)
#define XLO(b)   ((b) * 36864 + 18432)
#define BIAS_OFF 73728
#define SM_TOTAL 74240

__device__ __forceinline__ uint32_t smem_u32(const void* p) {
    uint32_t a;
    asm("{ .reg .u64 t; cvta.to.shared.u64 t, %1; cvt.u32.u64 %0, t; }" : "=r"(a) : "l"(p));
    return a;
}
__device__ __forceinline__ void ldsm_x4(uint32_t& r0, uint32_t& r1, uint32_t& r2, uint32_t& r3,
                                        uint32_t addr) {
    asm volatile("ldmatrix.sync.aligned.m8n8.x4.shared.b16 {%0,%1,%2,%3}, [%4];"
                 : "=r"(r0), "=r"(r1), "=r"(r2), "=r"(r3) : "r"(addr));
}
__device__ __forceinline__ void mma16816(float& c0, float& c1, float& c2, float& c3,
                                         uint32_t a0, uint32_t a1, uint32_t a2, uint32_t a3,
                                         uint32_t b0, uint32_t b1) {
    asm volatile("mma.sync.aligned.m16n8k16.row.col.f32.bf16.bf16.f32 "
                 "{%0,%1,%2,%3}, {%4,%5,%6,%7}, {%8,%9}, {%0,%1,%2,%3};"
                 : "+f"(c0), "+f"(c1), "+f"(c2), "+f"(c3)
                 : "r"(a0), "r"(a1), "r"(a2), "r"(a3), "r"(b0), "r"(b1));
}

// ---- W pre-packed as mma B-fragments: [k16][n8][reg][lane] -> uint2{hi,lo} ----
// Standard m16n8k16 B frag: reg0 = {B[2(l%4)][l/4], B[2(l%4)+1][l/4]},
// reg1 same at k+8.  B[k][n] == W[n][k].
__device__ __align__(16) uint2 g_Wfrag[NK16 * 16 * 2 * 32];

__global__ void prep_W_kernel(const float* __restrict__ W) {
    int i = blockIdx.x * blockDim.x + threadIdx.x;
    if (i >= NK16 * 16 * 2 * 32) return;
    int lane = i & 31;
    int reg  = (i >> 5) & 1;
    int n8   = (i >> 6) & 15;
    int k16  = i >> 10;
    int n_g  = n8 * 8 + (lane >> 2);
    int k_g  = k16 * 16 + (lane & 3) * 2 + reg * 8;
    float w0 = W[n_g * IN_D + k_g];
    float w1 = W[n_g * IN_D + k_g + 1];
    __nv_bfloat16 h0 = __float2bfloat16(w0), h1 = __float2bfloat16(w1);
    __nv_bfloat16 l0 = __float2bfloat16(w0 - __bfloat162float(h0));
    __nv_bfloat16 l1 = __float2bfloat16(w1 - __bfloat162float(h1));
    __nv_bfloat162 hv(h0, h1), lv(l0, l1);
    g_Wfrag[i] = make_uint2(*reinterpret_cast<uint32_t*>(&hv),
                            *reinterpret_cast<uint32_t*>(&lv));
}

__global__ void __launch_bounds__(THREADS, 2)
edgeblock_mma_kernel(const float* __restrict__ nodes,
                     const float* __restrict__ edges,
                     const int* __restrict__ recv,
                     const int* __restrict__ send,
                     const float* __restrict__ bias,
                     float* __restrict__ out,
                     int E)
{
    extern __shared__ char smem[];
    const uint32_t sm = smem_u32(smem);
    const int t = threadIdx.x;
    const int lane = t & 31, wid = t >> 5;
    const int e0 = blockIdx.x * TM;

    // warp tiling: 2 (m) x 4 (n)
    const int m_base  = (wid & 1) * 64;
    const int n8base  = (wid >> 1) * 4;       // first n8-tile of this warp

    float* Bs = (float*)(smem + BIAS_OFF);
    if (t < OUT_D) Bs[t] = bias[t];

    // per-thread staging role: 2 threads per X row
    const int sr = t >> 1;
    const int sh = t & 1;
    const int e_row = e0 + sr;
    const bool e_ok = e_row < E;
    const int ridx = e_ok ? recv[e_row] : 0;
    const int sidx = e_ok ? send[e_row] : 0;
    const float* xsrc0 = e_ok ? edges + (size_t)e_row * 128 : nullptr;
    const float* xsrc1 = nodes + (size_t)ridx * 128;
    const float* xsrc2 = nodes + (size_t)sidx * 128;

    // ldmatrix A per-lane address (validated)
    const int lr = lane & 7, g4 = lane >> 3;
    const uint32_t a_off = (uint32_t)(m_base + lr + (g4 & 1) * 8) * STR2 + (g4 >> 1) * 16;

    float acc[4][4][4];
#pragma unroll
    for (int i = 0; i < 4; ++i)
#pragma unroll
        for (int j = 0; j < 4; ++j)
#pragma unroll
            for (int k = 0; k < 4; ++k) acc[i][j][k] = 0.f;

    // ---- stage X chunk c into buffer b: LDG -> hi/lo cvt -> STS ----
    auto stage = [&](int c, int b) {
        const int xoff = (c & 1) * KC;
        const float* s = (c < 2) ? xsrc0 : (c < 4) ? xsrc1 : xsrc2;
        const uint32_t rbase = (uint32_t)sr * STR2 + sh * 64;
#pragma unroll
        for (int i = 0; i < 4; ++i) {
            float4 fa = make_float4(0.f, 0.f, 0.f, 0.f), fb = fa;
            if (s) {
                const float4* p = reinterpret_cast<const float4*>(s + xoff + sh * 32 + i * 8);
                fa = p[0]; fb = p[1];
            }
            const float f[8] = {fa.x, fa.y, fa.z, fa.w, fb.x, fb.y, fb.z, fb.w};
            __nv_bfloat16 hi[8], lo[8];
#pragma unroll
            for (int j = 0; j < 8; ++j) {
                hi[j] = __float2bfloat16(f[j]);
                lo[j] = __float2bfloat16(f[j] - __bfloat162float(hi[j]));
            }
            *reinterpret_cast<uint4*>(smem + XHI(b) + rbase + i * 16) = *reinterpret_cast<uint4*>(hi);
            *reinterpret_cast<uint4*>(smem + XLO(b) + rbase + i * 16) = *reinterpret_cast<uint4*>(lo);
        }
    };

    // ---- compute chunk c from buffer b ----
    auto compute = [&](int c, int b) {
#pragma unroll
        for (int kk = 0; kk < 4; ++kk) {
            const int k16g = c * 4 + kk;
            const uint32_t koff = kk * 32;       // 16 bf16 = 32 B
            // B frags straight from global (L2-broadcast)
            uint32_t bh[4][2], bl[4][2];
#pragma unroll
            for (int tn = 0; tn < 4; ++tn)
#pragma unroll
                for (int rg = 0; rg < 2; ++rg) {
                    uint2 v = __ldg(&g_Wfrag[(((k16g * 16) + n8base + tn) * 2 + rg) * 32 + lane]);
                    bh[tn][rg] = v.x;
                    bl[tn][rg] = v.y;
                }
            uint32_t a[4][4];
            // A hi: pass1 (Ahi*Whi) + pass2 (Ahi*Wlo)
#pragma unroll
            for (int tm = 0; tm < 4; ++tm)
                ldsm_x4(a[tm][0], a[tm][1], a[tm][2], a[tm][3],
                        sm + XHI(b) + a_off + tm * 16 * STR2 + koff);
#pragma unroll
            for (int tm = 0; tm < 4; ++tm)
#pragma unroll
                for (int tn = 0; tn < 4; ++tn) {
                    mma16816(acc[tm][tn][0], acc[tm][tn][1], acc[tm][tn][2], acc[tm][tn][3],
                             a[tm][0], a[tm][1], a[tm][2], a[tm][3], bh[tn][0], bh[tn][1]);
                    mma16816(acc[tm][tn][0], acc[tm][tn][1], acc[tm][tn][2], acc[tm][tn][3],
                             a[tm][0], a[tm][1], a[tm][2], a[tm][3], bl[tn][0], bl[tn][1]);
                }
            // A lo: pass3 (Alo*Whi)
#pragma unroll
            for (int tm = 0; tm < 4; ++tm)
                ldsm_x4(a[tm][0], a[tm][1], a[tm][2], a[tm][3],
                        sm + XLO(b) + a_off + tm * 16 * STR2 + koff);
#pragma unroll
            for (int tm = 0; tm < 4; ++tm)
#pragma unroll
                for (int tn = 0; tn < 4; ++tn)
                    mma16816(acc[tm][tn][0], acc[tm][tn][1], acc[tm][tn][2], acc[tm][tn][3],
                             a[tm][0], a[tm][1], a[tm][2], a[tm][3], bh[tn][0], bh[tn][1]);
        }
    };

    // ---- pipeline: stage(c+1) overlaps tail of compute(c); 1 sync per chunk ----
    stage(0, 0);
    __syncthreads();
    for (int c = 0; c < NCHUNK; ++c) {
        compute(c, c & 1);
        if (c + 1 < NCHUNK) stage(c + 1, (c + 1) & 1);
        __syncthreads();
    }

    // ---- epilogue ----
    const int gq = lane >> 2, t4 = lane & 3;
#pragma unroll
    for (int tm = 0; tm < 4; ++tm) {
        int r0 = e0 + m_base + tm * 16 + gq;
        int r1 = r0 + 8;
#pragma unroll
        for (int tn = 0; tn < 4; ++tn) {
            int cbase = n8base * 8 + tn * 8 + t4 * 2;
            float b0 = Bs[cbase], b1 = Bs[cbase + 1];
            if (r0 < E) {
                float2 v = make_float2(acc[tm][tn][0] + b0, acc[tm][tn][1] + b1);
                *reinterpret_cast<float2*>(out + (size_t)r0 * OUT_D + cbase) = v;
            }
            if (r1 < E) {
                float2 v = make_float2(acc[tm][tn][2] + b0, acc[tm][tn][3] + b1);
                *reinterpret_cast<float2*>(out + (size_t)r1 * OUT_D + cbase) = v;
            }
        }
    }
}

extern "C" void kernel_launch(void* const* d_in, const int* in_sizes, int n_in,
                              void* d_out, int out_size)
{
    const float* nodes = (const float*)d_in[0];
    const float* edges = (const float*)d_in[1];
    const int*   recv  = (const int*)d_in[2];
    const int*   send  = (const int*)d_in[3];
    const float* W     = (const float*)d_in[4];
    const float* bias  = (const float*)d_in[5];
    float*       out   = (float*)d_out;
    int E = in_sizes[2];

    cudaFuncSetAttribute(edgeblock_mma_kernel,
                         cudaFuncAttributeMaxDynamicSharedMemorySize, SM_TOTAL);

    prep_W_kernel<<<(NK16 * 16 * 2 * 32 + 255) / 256, 256>>>(W);
    int grid = (E + TM - 1) / TM;
    edgeblock_mma_kernel<<<grid, THREADS, SM_TOTAL>>>(nodes, edges, recv, send, bias, out, E);
}

// round 9
// speedup vs baseline: 1.2589x; 1.2589x over previous
#include <cuda_runtime.h>
#include <cuda_bf16.h>
#include <cstdint>

// EdgeBlock: out[e,:] = W @ concat(edges[e], nodes[recv[e]], nodes[send[e]]) + b
// E=500000, NODE_D=EDGE_D=128, IN_D=384, W [128,384] row-major, out [E,128] f32.
// mma.sync m16n8k16 bf16, 3-pass hi/lo split (validated rel_err 4.6e-6).
// R9: 3-stage cp.async pipeline of raw fp32 X; bf16 hi/lo conversion fused into
//     A-fragment build (no conversion/STS pass); B frags via L1-hot LDG.

#define IN_D    384
#define OUT_D   128
#define TM      128
#define KC      64
#define NCHUNK  6
#define NK16    24
#define THREADS 256
#define S_F32   68                  // f32 row stride (68 mod 32 == 4 -> bank-uniform)
#define BUFSZ   (TM * S_F32 * 4)    // 34816 B per stage
#define RIDX_OFF (3 * BUFSZ)        // 104448
#define SIDX_OFF (RIDX_OFF + 512)
#define BIAS_OFF (SIDX_OFF + 512)
#define SM_TOTAL (BIAS_OFF + 512)   // 105984

__device__ __forceinline__ uint32_t smem_u32(const void* p) {
    uint32_t a;
    asm("{ .reg .u64 t; cvta.to.shared.u64 t, %1; cvt.u32.u64 %0, t; }" : "=r"(a) : "l"(p));
    return a;
}
__device__ __forceinline__ void cp_async16(uint32_t dst, const void* src, int srcsz) {
    asm volatile("cp.async.cg.shared.global [%0], [%1], 16, %2;"
                 :: "r"(dst), "l"(src), "r"(srcsz) : "memory");
}
#define CP_COMMIT() asm volatile("cp.async.commit_group;" ::: "memory")
template <int N>
__device__ __forceinline__ void cp_wait() {
    asm volatile("cp.async.wait_group %0;" :: "n"(N) : "memory");
}
__device__ __forceinline__ void mma16816(float& c0, float& c1, float& c2, float& c3,
                                         uint32_t a0, uint32_t a1, uint32_t a2, uint32_t a3,
                                         uint32_t b0, uint32_t b1) {
    asm volatile("mma.sync.aligned.m16n8k16.row.col.f32.bf16.bf16.f32 "
                 "{%0,%1,%2,%3}, {%4,%5,%6,%7}, {%8,%9}, {%0,%1,%2,%3};"
                 : "+f"(c0), "+f"(c1), "+f"(c2), "+f"(c3)
                 : "r"(a0), "r"(a1), "r"(a2), "r"(a3), "r"(b0), "r"(b1));
}
// pack two f32 -> bf16x2 (lo = x, hi = y)
__device__ __forceinline__ uint32_t bf2(float x, float y) {
    uint32_t r;
    asm("cvt.rn.satfinite.bf16x2.f32 %0, %1, %2;" : "=r"(r) : "f"(y), "f"(x));
    return r;
}

// ---- W pre-packed as mma B-fragments: [k16][n8][reg][lane] -> uint2{hi,lo} ----
__device__ __align__(16) uint2 g_Wfrag[NK16 * 16 * 2 * 32];

__global__ void prep_W_kernel(const float* __restrict__ W) {
    int i = blockIdx.x * blockDim.x + threadIdx.x;
    if (i >= NK16 * 16 * 2 * 32) return;
    int lane = i & 31;
    int reg  = (i >> 5) & 1;
    int n8   = (i >> 6) & 15;
    int k16  = i >> 10;
    int n_g  = n8 * 8 + (lane >> 2);
    int k_g  = k16 * 16 + (lane & 3) * 2 + reg * 8;
    float w0 = W[n_g * IN_D + k_g];
    float w1 = W[n_g * IN_D + k_g + 1];
    __nv_bfloat16 h0 = __float2bfloat16(w0), h1 = __float2bfloat16(w1);
    __nv_bfloat16 l0 = __float2bfloat16(w0 - __bfloat162float(h0));
    __nv_bfloat16 l1 = __float2bfloat16(w1 - __bfloat162float(h1));
    __nv_bfloat162 hv(h0, h1), lv(l0, l1);
    g_Wfrag[i] = make_uint2(*reinterpret_cast<uint32_t*>(&hv),
                            *reinterpret_cast<uint32_t*>(&lv));
}

__global__ void __launch_bounds__(THREADS, 2)
edgeblock_mma_kernel(const float* __restrict__ nodes,
                     const float* __restrict__ edges,
                     const int* __restrict__ recv,
                     const int* __restrict__ send,
                     const float* __restrict__ bias,
                     float* __restrict__ out,
                     int E)
{
    extern __shared__ char smem[];
    const uint32_t sm = smem_u32(smem);
    const int t = threadIdx.x;
    const int lane = t & 31, wid = t >> 5;
    const int e0 = blockIdx.x * TM;

    const int m_base = (wid & 1) * 64;
    const int n8base = (wid >> 1) * 4;

    int* Ridx = (int*)(smem + RIDX_OFF);
    int* Sidx = (int*)(smem + SIDX_OFF);
    float* Bs = (float*)(smem + BIAS_OFF);
    if (t < TM) {
        int e = e0 + t;
        Ridx[t] = (e < E) ? recv[e] : 0;
        Sidx[t] = (e < E) ? send[e] : 0;
        Bs[t] = bias[t];
    }
    __syncthreads();

    // ---- cp.async staging of chunk c into buffer b (8 x 16B per thread) ----
    auto stage = [&](int c, int b) {
        const int coff = (c & 1) * KC;
#pragma unroll
        for (int i = 0; i < 8; ++i) {
            int idx = t + i * THREADS;        // 0..2047
            int row = idx >> 4, s = idx & 15; // 16 segs x 16B = 64 f32
            uint32_t dst = sm + b * BUFSZ + row * (S_F32 * 4) + s * 16;
            const float* srcp;
            int sz = 16;
            if (c < 2) {
                int e = e0 + row;
                if (e < E) srcp = edges + (size_t)e * 128 + coff + s * 4;
                else { srcp = edges; sz = 0; }
            } else if (c < 4) {
                srcp = nodes + (size_t)Ridx[row] * 128 + coff + s * 4;
            } else {
                srcp = nodes + (size_t)Sidx[row] * 128 + coff + s * 4;
            }
            cp_async16(dst, srcp, sz);
        }
        CP_COMMIT();
    };

    float acc[4][4][4];
#pragma unroll
    for (int i = 0; i < 4; ++i)
#pragma unroll
        for (int j = 0; j < 4; ++j)
#pragma unroll
            for (int k = 0; k < 4; ++k) acc[i][j][k] = 0.f;

    const int gq = lane >> 2, t4 = lane & 3;
    // A-load base: [m_base + gq] row, col 2*t4 (f32)
    const uint32_t abase = (uint32_t)(m_base + gq) * (S_F32 * 4) + (uint32_t)t4 * 8;

    // ---- compute chunk c from buffer b ----
    auto compute = [&](int c, int b) {
        const uint32_t bufb = sm + b * BUFSZ + abase;
#pragma unroll
        for (int kk = 0; kk < 4; ++kk) {
            const int k16g = c * 4 + kk;
            // B frags (L1-hot after first wave)
            uint32_t bh[4][2], bl[4][2];
#pragma unroll
            for (int tn = 0; tn < 4; ++tn)
#pragma unroll
                for (int rg = 0; rg < 2; ++rg) {
                    uint2 v = __ldg(&g_Wfrag[(((k16g * 16) + n8base + tn) * 2 + rg) * 32 + lane]);
                    bh[tn][rg] = v.x;
                    bl[tn][rg] = v.y;
                }
#pragma unroll
            for (int tm = 0; tm < 4; ++tm) {
                // load 4 float2 from fp32 tile, build hi/lo bf16x2 frags
                uint32_t ah[4], al[4];
#pragma unroll
                for (int rg = 0; rg < 4; ++rg) {
                    uint32_t addr = bufb + (uint32_t)(tm * 16 + (rg & 1) * 8) * (S_F32 * 4)
                                  + (uint32_t)(kk * 16 + (rg >> 1) * 8) * 4;
                    float2 f;
                    asm volatile("ld.shared.v2.f32 {%0,%1}, [%2];"
                                 : "=f"(f.x), "=f"(f.y) : "r"(addr));
                    uint32_t h = bf2(f.x, f.y);
                    float lx = f.x - __uint_as_float(h << 16);
                    float ly = f.y - __uint_as_float(h & 0xFFFF0000u);
                    ah[rg] = h;
                    al[rg] = bf2(lx, ly);
                }
#pragma unroll
                for (int tn = 0; tn < 4; ++tn) {
                    mma16816(acc[tm][tn][0], acc[tm][tn][1], acc[tm][tn][2], acc[tm][tn][3],
                             ah[0], ah[1], ah[2], ah[3], bh[tn][0], bh[tn][1]);
                    mma16816(acc[tm][tn][0], acc[tm][tn][1], acc[tm][tn][2], acc[tm][tn][3],
                             ah[0], ah[1], ah[2], ah[3], bl[tn][0], bl[tn][1]);
                    mma16816(acc[tm][tn][0], acc[tm][tn][1], acc[tm][tn][2], acc[tm][tn][3],
                             al[0], al[1], al[2], al[3], bh[tn][0], bh[tn][1]);
                }
            }
        }
    };

    // ---- 3-stage pipeline, chunk loop unrolled for compile-time wait counts ----
    stage(0, 0);
    stage(1, 1);
#pragma unroll
    for (int c = 0; c < NCHUNK; ++c) {
        if (c < NCHUNK - 1) cp_wait<1>(); else cp_wait<0>();
        __syncthreads();
        compute(c, c % 3);
        if (c + 2 < NCHUNK) stage(c + 2, (c + 2) % 3);
    }

    // ---- epilogue ----
#pragma unroll
    for (int tm = 0; tm < 4; ++tm) {
        int r0 = e0 + m_base + tm * 16 + gq;
        int r1 = r0 + 8;
#pragma unroll
        for (int tn = 0; tn < 4; ++tn) {
            int cbase = n8base * 8 + tn * 8 + t4 * 2;
            float b0 = Bs[cbase], b1 = Bs[cbase + 1];
            if (r0 < E) {
                float2 v = make_float2(acc[tm][tn][0] + b0, acc[tm][tn][1] + b1);
                *reinterpret_cast<float2*>(out + (size_t)r0 * OUT_D + cbase) = v;
            }
            if (r1 < E) {
                float2 v = make_float2(acc[tm][tn][2] + b0, acc[tm][tn][3] + b1);
                *reinterpret_cast<float2*>(out + (size_t)r1 * OUT_D + cbase) = v;
            }
        }
    }
}

extern "C" void kernel_launch(void* const* d_in, const int* in_sizes, int n_in,
                              void* d_out, int out_size)
{
    const float* nodes = (const float*)d_in[0];
    const float* edges = (const float*)d_in[1];
    const int*   recv  = (const int*)d_in[2];
    const int*   send  = (const int*)d_in[3];
    const float* W     = (const float*)d_in[4];
    const float* bias  = (const float*)d_in[5];
    float*       out   = (float*)d_out;
    int E = in_sizes[2];

    cudaFuncSetAttribute(edgeblock_mma_kernel,
                         cudaFuncAttributeMaxDynamicSharedMemorySize, SM_TOTAL);

    prep_W_kernel<<<(NK16 * 16 * 2 * 32 + 255) / 256, 256>>>(W);
    int grid = (E + TM - 1) / TM;
    edgeblock_mma_kernel<<<grid, THREADS, SM_TOTAL>>>(nodes, edges, recv, send, bias, out, E);
}

// round 10
// speedup vs baseline: 1.2868x; 1.0222x over previous
#include <cuda_runtime.h>
#include <cuda_bf16.h>
#include <cstdint>

// EdgeBlock: out[e,:] = W @ concat(edges[e], nodes[recv[e]], nodes[send[e]]) + b
// E=500000, NODE_D=EDGE_D=128, IN_D=384, W [128,384] row-major, out [E,128] f32.
// mma.sync m16n8k16 bf16, 3-pass hi/lo split (validated rel_err 4.6e-6).
// R10: nodes pre-split to bf16 hi/lo tables (reused ~20x) -> node chunks are
//      pure cp.async + LDSM + MMA; edge chunks keep R9 inline conversion.

#define IN_D    384
#define OUT_D   128
#define TM      128
#define KC      64
#define NCHUNK  6
#define NK16    24
#define THREADS 256
#define N_NODES_MAX 50000

#define S_F32   68                   // f32 row stride for edge buffers (272 B)
#define STRB    144                  // bf16 row stride for node buffers
#define BUFSZ   36864                // per-stage buffer (fits both formats)
#define LO_OFF  18432                // lo half inside a node-format buffer
#define RIDX_OFF (3 * BUFSZ)         // 110592
#define SIDX_OFF (RIDX_OFF + 512)
#define BIAS_OFF (SIDX_OFF + 512)
#define SM_TOTAL (BIAS_OFF + 512)    // 112128

__device__ __forceinline__ uint32_t smem_u32(const void* p) {
    uint32_t a;
    asm("{ .reg .u64 t; cvta.to.shared.u64 t, %1; cvt.u32.u64 %0, t; }" : "=r"(a) : "l"(p));
    return a;
}
__device__ __forceinline__ void cp_async16(uint32_t dst, const void* src, int srcsz) {
    asm volatile("cp.async.cg.shared.global [%0], [%1], 16, %2;"
                 :: "r"(dst), "l"(src), "r"(srcsz) : "memory");
}
#define CP_COMMIT() asm volatile("cp.async.commit_group;" ::: "memory")
template <int N>
__device__ __forceinline__ void cp_wait() {
    asm volatile("cp.async.wait_group %0;" :: "n"(N) : "memory");
}
__device__ __forceinline__ void ldsm_x4(uint32_t& r0, uint32_t& r1, uint32_t& r2, uint32_t& r3,
                                        uint32_t addr) {
    asm volatile("ldmatrix.sync.aligned.m8n8.x4.shared.b16 {%0,%1,%2,%3}, [%4];"
                 : "=r"(r0), "=r"(r1), "=r"(r2), "=r"(r3) : "r"(addr));
}
__device__ __forceinline__ void mma16816(float& c0, float& c1, float& c2, float& c3,
                                         uint32_t a0, uint32_t a1, uint32_t a2, uint32_t a3,
                                         uint32_t b0, uint32_t b1) {
    asm volatile("mma.sync.aligned.m16n8k16.row.col.f32.bf16.bf16.f32 "
                 "{%0,%1,%2,%3}, {%4,%5,%6,%7}, {%8,%9}, {%0,%1,%2,%3};"
                 : "+f"(c0), "+f"(c1), "+f"(c2), "+f"(c3)
                 : "r"(a0), "r"(a1), "r"(a2), "r"(a3), "r"(b0), "r"(b1));
}
__device__ __forceinline__ uint32_t bf2(float x, float y) {
    uint32_t r;
    asm("cvt.rn.satfinite.bf16x2.f32 %0, %1, %2;" : "=r"(r) : "f"(y), "f"(x));
    return r;
}

// ---- W pre-packed as mma B-fragments: [k16][n8][reg][lane] -> uint2{hi,lo} ----
__device__ __align__(16) uint2 g_Wfrag[NK16 * 16 * 2 * 32];
// ---- nodes pre-split to bf16 hi/lo, [node][128] row-major ----
__device__ __align__(16) __nv_bfloat16 g_Nhi[(size_t)N_NODES_MAX * 128];
__device__ __align__(16) __nv_bfloat16 g_Nlo[(size_t)N_NODES_MAX * 128];

__global__ void prep_W_kernel(const float* __restrict__ W) {
    int i = blockIdx.x * blockDim.x + threadIdx.x;
    if (i >= NK16 * 16 * 2 * 32) return;
    int lane = i & 31;
    int reg  = (i >> 5) & 1;
    int n8   = (i >> 6) & 15;
    int k16  = i >> 10;
    int n_g  = n8 * 8 + (lane >> 2);
    int k_g  = k16 * 16 + (lane & 3) * 2 + reg * 8;
    float w0 = W[n_g * IN_D + k_g];
    float w1 = W[n_g * IN_D + k_g + 1];
    __nv_bfloat16 h0 = __float2bfloat16(w0), h1 = __float2bfloat16(w1);
    __nv_bfloat16 l0 = __float2bfloat16(w0 - __bfloat162float(h0));
    __nv_bfloat16 l1 = __float2bfloat16(w1 - __bfloat162float(h1));
    __nv_bfloat162 hv(h0, h1), lv(l0, l1);
    g_Wfrag[i] = make_uint2(*reinterpret_cast<uint32_t*>(&hv),
                            *reinterpret_cast<uint32_t*>(&lv));
}

__global__ void prep_nodes_kernel(const float* __restrict__ nodes, int total4) {
    int i = blockIdx.x * blockDim.x + threadIdx.x;   // over float4 groups
    if (i >= total4) return;
    float4 v = reinterpret_cast<const float4*>(nodes)[i];
    const float f[4] = {v.x, v.y, v.z, v.w};
    __nv_bfloat16 hi[4], lo[4];
#pragma unroll
    for (int j = 0; j < 4; ++j) {
        hi[j] = __float2bfloat16(f[j]);
        lo[j] = __float2bfloat16(f[j] - __bfloat162float(hi[j]));
    }
    *reinterpret_cast<uint2*>(g_Nhi + i * 4) = *reinterpret_cast<uint2*>(hi);
    *reinterpret_cast<uint2*>(g_Nlo + i * 4) = *reinterpret_cast<uint2*>(lo);
}

__global__ void __launch_bounds__(THREADS, 2)
edgeblock_mma_kernel(const float* __restrict__ edges,
                     const int* __restrict__ recv,
                     const int* __restrict__ send,
                     const float* __restrict__ bias,
                     float* __restrict__ out,
                     int E)
{
    extern __shared__ char smem[];
    const uint32_t sm = smem_u32(smem);
    const int t = threadIdx.x;
    const int lane = t & 31, wid = t >> 5;
    const int e0 = blockIdx.x * TM;

    const int m_base = (wid & 1) * 64;
    const int n8base = (wid >> 1) * 4;

    int* Ridx = (int*)(smem + RIDX_OFF);
    int* Sidx = (int*)(smem + SIDX_OFF);
    float* Bs = (float*)(smem + BIAS_OFF);
    if (t < TM) {
        int e = e0 + t;
        Ridx[t] = (e < E) ? recv[e] : 0;
        Sidx[t] = (e < E) ? send[e] : 0;
        Bs[t] = bias[t];
    }
    __syncthreads();

    // ---- staging ----
    // edge chunk (c<2): fp32, 16 segs/row;  node chunk: bf16 hi+lo, 8+8 segs/row
    auto stage = [&](int c, int b) {
        const uint32_t buf = sm + b * BUFSZ;
        if (c < 2) {
            const int coff = (c & 1) * KC;
#pragma unroll
            for (int i = 0; i < 8; ++i) {
                int idx = t + i * THREADS;
                int row = idx >> 4, s = idx & 15;
                uint32_t dst = buf + row * (S_F32 * 4) + s * 16;
                int e = e0 + row;
                const float* srcp = edges + (size_t)(e < E ? e : 0) * 128 + coff + s * 4;
                cp_async16(dst, srcp, (e < E) ? 16 : 0);
            }
        } else {
            const int coff = (c & 1) * KC;
            const int* idxs = (c < 4) ? Ridx : Sidx;
#pragma unroll
            for (int i = 0; i < 8; ++i) {
                int idx = t + i * THREADS;
                int row = idx >> 4, p = idx & 15;       // p<8: hi seg p, else lo seg p-8
                int node = idxs[row];
                size_t ebase = ((size_t)node * 128 + coff) * 2;
                if (p < 8) {
                    cp_async16(buf + row * STRB + p * 16,
                               (const char*)g_Nhi + ebase + p * 16, 16);
                } else {
                    cp_async16(buf + LO_OFF + row * STRB + (p - 8) * 16,
                               (const char*)g_Nlo + ebase + (p - 8) * 16, 16);
                }
            }
        }
        CP_COMMIT();
    };

    float acc[4][4][4];
#pragma unroll
    for (int i = 0; i < 4; ++i)
#pragma unroll
        for (int j = 0; j < 4; ++j)
#pragma unroll
            for (int k = 0; k < 4; ++k) acc[i][j][k] = 0.f;

    const int gq = lane >> 2, t4 = lane & 3;
    const int lr = lane & 7, g4 = lane >> 3;
    // fp32 inline A base (edge chunks)
    const uint32_t abase_f32 = (uint32_t)(m_base + gq) * (S_F32 * 4) + (uint32_t)t4 * 8;
    // ldmatrix A base (node chunks)
    const uint32_t abase_ldsm = (uint32_t)(m_base + lr + (g4 & 1) * 8) * STRB + (g4 >> 1) * 16;

    auto ldB = [&](int k16g, uint32_t (&bh)[4][2], uint32_t (&bl)[4][2]) {
#pragma unroll
        for (int tn = 0; tn < 4; ++tn)
#pragma unroll
            for (int rg = 0; rg < 2; ++rg) {
                uint2 v = __ldg(&g_Wfrag[(((k16g * 16) + n8base + tn) * 2 + rg) * 32 + lane]);
                bh[tn][rg] = v.x;
                bl[tn][rg] = v.y;
            }
    };
    auto mma3 = [&](int tm, uint32_t (&ah)[4], uint32_t (&al)[4],
                    uint32_t (&bh)[4][2], uint32_t (&bl)[4][2]) {
#pragma unroll
        for (int tn = 0; tn < 4; ++tn) {
            mma16816(acc[tm][tn][0], acc[tm][tn][1], acc[tm][tn][2], acc[tm][tn][3],
                     ah[0], ah[1], ah[2], ah[3], bh[tn][0], bh[tn][1]);
            mma16816(acc[tm][tn][0], acc[tm][tn][1], acc[tm][tn][2], acc[tm][tn][3],
                     ah[0], ah[1], ah[2], ah[3], bl[tn][0], bl[tn][1]);
            mma16816(acc[tm][tn][0], acc[tm][tn][1], acc[tm][tn][2], acc[tm][tn][3],
                     al[0], al[1], al[2], al[3], bh[tn][0], bh[tn][1]);
        }
    };

    // ---- compute: edge chunk (inline cvt) ----
    auto compute_edge = [&](int c, int b) {
        const uint32_t bufb = sm + b * BUFSZ + abase_f32;
#pragma unroll
        for (int kk = 0; kk < 4; ++kk) {
            uint32_t bh[4][2], bl[4][2];
            ldB(c * 4 + kk, bh, bl);
#pragma unroll
            for (int tm = 0; tm < 4; ++tm) {
                uint32_t ah[4], al[4];
#pragma unroll
                for (int rg = 0; rg < 4; ++rg) {
                    uint32_t addr = bufb + (uint32_t)(tm * 16 + (rg & 1) * 8) * (S_F32 * 4)
                                  + (uint32_t)(kk * 16 + (rg >> 1) * 8) * 4;
                    float2 f;
                    asm volatile("ld.shared.v2.f32 {%0,%1}, [%2];"
                                 : "=f"(f.x), "=f"(f.y) : "r"(addr));
                    uint32_t h = bf2(f.x, f.y);
                    float lx = f.x - __uint_as_float(h << 16);
                    float ly = f.y - __uint_as_float(h & 0xFFFF0000u);
                    ah[rg] = h;
                    al[rg] = bf2(lx, ly);
                }
                mma3(tm, ah, al, bh, bl);
            }
        }
    };
    // ---- compute: node chunk (pure LDSM) ----
    auto compute_node = [&](int c, int b) {
        const uint32_t hb = sm + b * BUFSZ + abase_ldsm;
#pragma unroll
        for (int kk = 0; kk < 4; ++kk) {
            uint32_t bh[4][2], bl[4][2];
            ldB(c * 4 + kk, bh, bl);
#pragma unroll
            for (int tm = 0; tm < 4; ++tm) {
                uint32_t ah[4], al[4];
                uint32_t base = hb + tm * 16 * STRB + kk * 32;
                ldsm_x4(ah[0], ah[1], ah[2], ah[3], base);
                ldsm_x4(al[0], al[1], al[2], al[3], base + LO_OFF);
                mma3(tm, ah, al, bh, bl);
            }
        }
    };

    // ---- 3-stage pipeline ----
    stage(0, 0);
    stage(1, 1);
#pragma unroll
    for (int c = 0; c < NCHUNK; ++c) {
        if (c < NCHUNK - 1) cp_wait<1>(); else cp_wait<0>();
        __syncthreads();
        if (c < 2) compute_edge(c, c % 3);
        else       compute_node(c, c % 3);
        if (c + 2 < NCHUNK) stage(c + 2, (c + 2) % 3);
    }

    // ---- epilogue ----
#pragma unroll
    for (int tm = 0; tm < 4; ++tm) {
        int r0 = e0 + m_base + tm * 16 + gq;
        int r1 = r0 + 8;
#pragma unroll
        for (int tn = 0; tn < 4; ++tn) {
            int cbase = n8base * 8 + tn * 8 + t4 * 2;
            float b0 = Bs[cbase], b1 = Bs[cbase + 1];
            if (r0 < E) {
                float2 v = make_float2(acc[tm][tn][0] + b0, acc[tm][tn][1] + b1);
                *reinterpret_cast<float2*>(out + (size_t)r0 * OUT_D + cbase) = v;
            }
            if (r1 < E) {
                float2 v = make_float2(acc[tm][tn][2] + b0, acc[tm][tn][3] + b1);
                *reinterpret_cast<float2*>(out + (size_t)r1 * OUT_D + cbase) = v;
            }
        }
    }
}

extern "C" void kernel_launch(void* const* d_in, const int* in_sizes, int n_in,
                              void* d_out, int out_size)
{
    const float* nodes = (const float*)d_in[0];
    const float* edges = (const float*)d_in[1];
    const int*   recv  = (const int*)d_in[2];
    const int*   send  = (const int*)d_in[3];
    const float* W     = (const float*)d_in[4];
    const float* bias  = (const float*)d_in[5];
    float*       out   = (float*)d_out;
    int E = in_sizes[2];
    int n_node_f = in_sizes[0];              // N_NODES * 128

    cudaFuncSetAttribute(edgeblock_mma_kernel,
                         cudaFuncAttributeMaxDynamicSharedMemorySize, SM_TOTAL);

    prep_W_kernel<<<(NK16 * 16 * 2 * 32 + 255) / 256, 256>>>(W);
    int total4 = n_node_f / 4;
    prep_nodes_kernel<<<(total4 + 255) / 256, 256>>>(nodes, total4);
    int grid = (E + TM - 1) / TM;
    edgeblock_mma_kernel<<<grid, THREADS, SM_TOTAL>>>(edges, recv, send, bias, out, E);
}

// round 11
// speedup vs baseline: 1.9656x; 1.5275x over previous
#include <cuda_runtime.h>
#include <cuda_fp16.h>
#include <cstdint>

// EdgeBlock: out[e,:] = W @ concat(edges[e], nodes[recv[e]], nodes[send[e]]) + b
// E=500000, NODE_D=EDGE_D=128, IN_D=384, W [128,384] row-major, out [E,128] f32.
// R11: fp16 mma m16n8k16, 2-pass W-split (wh+wl fp16, W exact to 2^-24;
//      X single fp16, rel_err ~2.8e-4). Nodes pre-converted to fp16 table.

#define IN_D    384
#define OUT_D   128
#define TM      128
#define KC      64
#define NCHUNK  6
#define NK16    24
#define THREADS 256
#define N_NODES_MAX 50000

#define S_F32   68                   // f32 row stride for edge buffers (272 B)
#define STRB    144                  // fp16 row stride for node buffers (bytes)
#define BUFSZ   36864                // per-stage buffer (fits both formats)
#define RIDX_OFF (3 * BUFSZ)         // 110592
#define SIDX_OFF (RIDX_OFF + 512)
#define BIAS_OFF (SIDX_OFF + 512)
#define SM_TOTAL (BIAS_OFF + 512)    // 112128

__device__ __forceinline__ uint32_t smem_u32(const void* p) {
    uint32_t a;
    asm("{ .reg .u64 t; cvta.to.shared.u64 t, %1; cvt.u32.u64 %0, t; }" : "=r"(a) : "l"(p));
    return a;
}
__device__ __forceinline__ void cp_async16(uint32_t dst, const void* src, int srcsz) {
    asm volatile("cp.async.cg.shared.global [%0], [%1], 16, %2;"
                 :: "r"(dst), "l"(src), "r"(srcsz) : "memory");
}
#define CP_COMMIT() asm volatile("cp.async.commit_group;" ::: "memory")
template <int N>
__device__ __forceinline__ void cp_wait() {
    asm volatile("cp.async.wait_group %0;" :: "n"(N) : "memory");
}
__device__ __forceinline__ void ldsm_x4(uint32_t& r0, uint32_t& r1, uint32_t& r2, uint32_t& r3,
                                        uint32_t addr) {
    asm volatile("ldmatrix.sync.aligned.m8n8.x4.shared.b16 {%0,%1,%2,%3}, [%4];"
                 : "=r"(r0), "=r"(r1), "=r"(r2), "=r"(r3) : "r"(addr));
}
__device__ __forceinline__ void mma16816(float& c0, float& c1, float& c2, float& c3,
                                         uint32_t a0, uint32_t a1, uint32_t a2, uint32_t a3,
                                         uint32_t b0, uint32_t b1) {
    asm volatile("mma.sync.aligned.m16n8k16.row.col.f32.f16.f16.f32 "
                 "{%0,%1,%2,%3}, {%4,%5,%6,%7}, {%8,%9}, {%0,%1,%2,%3};"
                 : "+f"(c0), "+f"(c1), "+f"(c2), "+f"(c3)
                 : "r"(a0), "r"(a1), "r"(a2), "r"(a3), "r"(b0), "r"(b1));
}
// pack two f32 -> f16x2 (lo = x, hi = y)
__device__ __forceinline__ uint32_t f16x2(float x, float y) {
    uint32_t r;
    asm("cvt.rn.f16x2.f32 %0, %1, %2;" : "=r"(r) : "f"(y), "f"(x));
    return r;
}

// ---- W pre-packed as mma B-fragments: [k16][n8][reg][lane] -> uint2{wh,wl} ----
__device__ __align__(16) uint2 g_Wfrag[NK16 * 16 * 2 * 32];
// ---- nodes pre-converted to fp16, [node][128] row-major ----
__device__ __align__(16) __half g_Nf16[(size_t)N_NODES_MAX * 128];

__global__ void prep_W_kernel(const float* __restrict__ W) {
    int i = blockIdx.x * blockDim.x + threadIdx.x;
    if (i >= NK16 * 16 * 2 * 32) return;
    int lane = i & 31;
    int reg  = (i >> 5) & 1;
    int n8   = (i >> 6) & 15;
    int k16  = i >> 10;
    int n_g  = n8 * 8 + (lane >> 2);
    int k_g  = k16 * 16 + (lane & 3) * 2 + reg * 8;
    float w0 = W[n_g * IN_D + k_g];
    float w1 = W[n_g * IN_D + k_g + 1];
    __half h0 = __float2half_rn(w0), h1 = __float2half_rn(w1);
    __half l0 = __float2half_rn(w0 - __half2float(h0));
    __half l1 = __float2half_rn(w1 - __half2float(h1));
    __half2 hv(h0, h1), lv(l0, l1);
    g_Wfrag[i] = make_uint2(*reinterpret_cast<uint32_t*>(&hv),
                            *reinterpret_cast<uint32_t*>(&lv));
}

__global__ void prep_nodes_kernel(const float* __restrict__ nodes, int total4) {
    int i = blockIdx.x * blockDim.x + threadIdx.x;   // over float4 groups
    if (i >= total4) return;
    float4 v = reinterpret_cast<const float4*>(nodes)[i];
    __half h[4] = {__float2half_rn(v.x), __float2half_rn(v.y),
                   __float2half_rn(v.z), __float2half_rn(v.w)};
    *reinterpret_cast<uint2*>(g_Nf16 + i * 4) = *reinterpret_cast<uint2*>(h);
}

__global__ void __launch_bounds__(THREADS, 2)
edgeblock_mma_kernel(const float* __restrict__ edges,
                     const int* __restrict__ recv,
                     const int* __restrict__ send,
                     const float* __restrict__ bias,
                     float* __restrict__ out,
                     int E)
{
    extern __shared__ char smem[];
    const uint32_t sm = smem_u32(smem);
    const int t = threadIdx.x;
    const int lane = t & 31, wid = t >> 5;
    const int e0 = blockIdx.x * TM;

    const int m_base = (wid & 1) * 64;
    const int n8base = (wid >> 1) * 4;

    int* Ridx = (int*)(smem + RIDX_OFF);
    int* Sidx = (int*)(smem + SIDX_OFF);
    float* Bs = (float*)(smem + BIAS_OFF);
    if (t < TM) {
        int e = e0 + t;
        Ridx[t] = (e < E) ? recv[e] : 0;
        Sidx[t] = (e < E) ? send[e] : 0;
        Bs[t] = bias[t];
    }
    __syncthreads();

    // ---- staging ----
    // edge chunk (c<2): fp32, 16 segs/row (8 cp/thread)
    // node chunk: fp16, 8 segs/row (4 cp/thread)
    auto stage = [&](int c, int b) {
        const uint32_t buf = sm + b * BUFSZ;
        const int coff = (c & 1) * KC;
        if (c < 2) {
#pragma unroll
            for (int i = 0; i < 8; ++i) {
                int idx = t + i * THREADS;
                int row = idx >> 4, s = idx & 15;
                uint32_t dst = buf + row * (S_F32 * 4) + s * 16;
                int e = e0 + row;
                const float* srcp = edges + (size_t)(e < E ? e : 0) * 128 + coff + s * 4;
                cp_async16(dst, srcp, (e < E) ? 16 : 0);
            }
        } else {
            const int* idxs = (c < 4) ? Ridx : Sidx;
#pragma unroll
            for (int i = 0; i < 4; ++i) {
                int idx = t + i * THREADS;
                int row = idx >> 3, p = idx & 7;
                int node = idxs[row];
                const char* srcp = (const char*)g_Nf16
                                 + ((size_t)node * 128 + coff) * 2 + p * 16;
                cp_async16(buf + row * STRB + p * 16, srcp, 16);
            }
        }
        CP_COMMIT();
    };

    float acc[4][4][4];
#pragma unroll
    for (int i = 0; i < 4; ++i)
#pragma unroll
        for (int j = 0; j < 4; ++j)
#pragma unroll
            for (int k = 0; k < 4; ++k) acc[i][j][k] = 0.f;

    const int gq = lane >> 2, t4 = lane & 3;
    const int lr = lane & 7, g4 = lane >> 3;
    const uint32_t abase_f32  = (uint32_t)(m_base + gq) * (S_F32 * 4) + (uint32_t)t4 * 8;
    const uint32_t abase_ldsm = (uint32_t)(m_base + lr + (g4 & 1) * 8) * STRB + (g4 >> 1) * 16;

    auto ldB = [&](int k16g, uint32_t (&bh)[4][2], uint32_t (&bl)[4][2]) {
#pragma unroll
        for (int tn = 0; tn < 4; ++tn)
#pragma unroll
            for (int rg = 0; rg < 2; ++rg) {
                uint2 v = __ldg(&g_Wfrag[(((k16g * 16) + n8base + tn) * 2 + rg) * 32 + lane]);
                bh[tn][rg] = v.x;
                bl[tn][rg] = v.y;
            }
    };
    // 2 passes: a*(wh) + a*(wl)  ->  a * w exact to 2^-24 in W
    auto mma2 = [&](int tm, uint32_t (&a)[4],
                    uint32_t (&bh)[4][2], uint32_t (&bl)[4][2]) {
#pragma unroll
        for (int tn = 0; tn < 4; ++tn) {
            mma16816(acc[tm][tn][0], acc[tm][tn][1], acc[tm][tn][2], acc[tm][tn][3],
                     a[0], a[1], a[2], a[3], bh[tn][0], bh[tn][1]);
            mma16816(acc[tm][tn][0], acc[tm][tn][1], acc[tm][tn][2], acc[tm][tn][3],
                     a[0], a[1], a[2], a[3], bl[tn][0], bl[tn][1]);
        }
    };

    // ---- compute: edge chunk (inline fp32 -> f16x2) ----
    auto compute_edge = [&](int c, int b) {
        const uint32_t bufb = sm + b * BUFSZ + abase_f32;
#pragma unroll
        for (int kk = 0; kk < 4; ++kk) {
            uint32_t bh[4][2], bl[4][2];
            ldB(c * 4 + kk, bh, bl);
#pragma unroll
            for (int tm = 0; tm < 4; ++tm) {
                uint32_t a[4];
#pragma unroll
                for (int rg = 0; rg < 4; ++rg) {
                    uint32_t addr = bufb + (uint32_t)(tm * 16 + (rg & 1) * 8) * (S_F32 * 4)
                                  + (uint32_t)(kk * 16 + (rg >> 1) * 8) * 4;
                    float2 f;
                    asm volatile("ld.shared.v2.f32 {%0,%1}, [%2];"
                                 : "=f"(f.x), "=f"(f.y) : "r"(addr));
                    a[rg] = f16x2(f.x, f.y);
                }
                mma2(tm, a, bh, bl);
            }
        }
    };
    // ---- compute: node chunk (pure LDSM) ----
    auto compute_node = [&](int c, int b) {
        const uint32_t hb = sm + b * BUFSZ + abase_ldsm;
#pragma unroll
        for (int kk = 0; kk < 4; ++kk) {
            uint32_t bh[4][2], bl[4][2];
            ldB(c * 4 + kk, bh, bl);
#pragma unroll
            for (int tm = 0; tm < 4; ++tm) {
                uint32_t a[4];
                ldsm_x4(a[0], a[1], a[2], a[3], hb + tm * 16 * STRB + kk * 32);
                mma2(tm, a, bh, bl);
            }
        }
    };

    // ---- 3-stage pipeline ----
    stage(0, 0);
    stage(1, 1);
#pragma unroll
    for (int c = 0; c < NCHUNK; ++c) {
        if (c < NCHUNK - 1) cp_wait<1>(); else cp_wait<0>();
        __syncthreads();
        if (c < 2) compute_edge(c, c % 3);
        else       compute_node(c, c % 3);
        if (c + 2 < NCHUNK) stage(c + 2, (c + 2) % 3);
    }

    // ---- epilogue ----
#pragma unroll
    for (int tm = 0; tm < 4; ++tm) {
        int r0 = e0 + m_base + tm * 16 + gq;
        int r1 = r0 + 8;
#pragma unroll
        for (int tn = 0; tn < 4; ++tn) {
            int cbase = n8base * 8 + tn * 8 + t4 * 2;
            float b0 = Bs[cbase], b1 = Bs[cbase + 1];
            if (r0 < E) {
                float2 v = make_float2(acc[tm][tn][0] + b0, acc[tm][tn][1] + b1);
                *reinterpret_cast<float2*>(out + (size_t)r0 * OUT_D + cbase) = v;
            }
            if (r1 < E) {
                float2 v = make_float2(acc[tm][tn][2] + b0, acc[tm][tn][3] + b1);
                *reinterpret_cast<float2*>(out + (size_t)r1 * OUT_D + cbase) = v;
            }
        }
    }
}

extern "C" void kernel_launch(void* const* d_in, const int* in_sizes, int n_in,
                              void* d_out, int out_size)
{
    const float* nodes = (const float*)d_in[0];
    const float* edges = (const float*)d_in[1];
    const int*   recv  = (const int*)d_in[2];
    const int*   send  = (const int*)d_in[3];
    const float* W     = (const float*)d_in[4];
    const float* bias  = (const float*)d_in[5];
    float*       out   = (float*)d_out;
    int E = in_sizes[2];
    int n_node_f = in_sizes[0];              // N_NODES * 128

    cudaFuncSetAttribute(edgeblock_mma_kernel,
                         cudaFuncAttributeMaxDynamicSharedMemorySize, SM_TOTAL);

    prep_W_kernel<<<(NK16 * 16 * 2 * 32 + 255) / 256, 256>>>(W);
    int total4 = n_node_f / 4;
    prep_nodes_kernel<<<(total4 + 255) / 256, 256>>>(nodes, total4);
    int grid = (E + TM - 1) / TM;
    edgeblock_mma_kernel<<<grid, THREADS, SM_TOTAL>>>(edges, recv, send, bias, out, E);
}

// round 12
// speedup vs baseline: 2.6496x; 1.3480x over previous
#include <cuda_runtime.h>
#include <cuda_fp16.h>
#include <cstdint>

// EdgeBlock: out[e,:] = W @ concat(edges[e], nodes[recv[e]], nodes[send[e]]) + b
// E=500000, NODE_D=EDGE_D=128, IN_D=384, W [128,384] row-major, out [E,128] f32.
// R12: single-pass fp16 mma m16n8k16 (X and W both fp16, fp32 accum).
//      Measured-anchor error model: R11 (X-only trunc) = 2.08e-4; adding W
//      trunc in quadrature -> ~2.9e-4 << 1e-3.

#define IN_D    384
#define OUT_D   128
#define TM      128
#define KC      64
#define NCHUNK  6
#define NK16    24
#define THREADS 256
#define N_NODES_MAX 50000

#define S_F32   68                   // f32 row stride for edge buffers (272 B)
#define STRB    144                  // fp16 row stride for node buffers (bytes)
#define BUFSZ   36864                // per-stage buffer (fits both formats)
#define RIDX_OFF (3 * BUFSZ)         // 110592
#define SIDX_OFF (RIDX_OFF + 512)
#define BIAS_OFF (SIDX_OFF + 512)
#define SM_TOTAL (BIAS_OFF + 512)    // 112128

__device__ __forceinline__ uint32_t smem_u32(const void* p) {
    uint32_t a;
    asm("{ .reg .u64 t; cvta.to.shared.u64 t, %1; cvt.u32.u64 %0, t; }" : "=r"(a) : "l"(p));
    return a;
}
__device__ __forceinline__ void cp_async16(uint32_t dst, const void* src, int srcsz) {
    asm volatile("cp.async.cg.shared.global [%0], [%1], 16, %2;"
                 :: "r"(dst), "l"(src), "r"(srcsz) : "memory");
}
#define CP_COMMIT() asm volatile("cp.async.commit_group;" ::: "memory")
template <int N>
__device__ __forceinline__ void cp_wait() {
    asm volatile("cp.async.wait_group %0;" :: "n"(N) : "memory");
}
__device__ __forceinline__ void ldsm_x4(uint32_t& r0, uint32_t& r1, uint32_t& r2, uint32_t& r3,
                                        uint32_t addr) {
    asm volatile("ldmatrix.sync.aligned.m8n8.x4.shared.b16 {%0,%1,%2,%3}, [%4];"
                 : "=r"(r0), "=r"(r1), "=r"(r2), "=r"(r3) : "r"(addr));
}
__device__ __forceinline__ void mma16816(float& c0, float& c1, float& c2, float& c3,
                                         uint32_t a0, uint32_t a1, uint32_t a2, uint32_t a3,
                                         uint32_t b0, uint32_t b1) {
    asm volatile("mma.sync.aligned.m16n8k16.row.col.f32.f16.f16.f32 "
                 "{%0,%1,%2,%3}, {%4,%5,%6,%7}, {%8,%9}, {%0,%1,%2,%3};"
                 : "+f"(c0), "+f"(c1), "+f"(c2), "+f"(c3)
                 : "r"(a0), "r"(a1), "r"(a2), "r"(a3), "r"(b0), "r"(b1));
}
__device__ __forceinline__ uint32_t f16x2(float x, float y) {
    uint32_t r;
    asm("cvt.rn.f16x2.f32 %0, %1, %2;" : "=r"(r) : "f"(y), "f"(x));
    return r;
}

// ---- W pre-packed as mma B-fragments: [k16][n8][reg][lane] -> uint32 f16x2 ----
__device__ __align__(16) uint32_t g_Wfrag[NK16 * 16 * 2 * 32];
// ---- nodes pre-converted to fp16, [node][128] row-major ----
__device__ __align__(16) __half g_Nf16[(size_t)N_NODES_MAX * 128];

__global__ void prep_W_kernel(const float* __restrict__ W) {
    int i = blockIdx.x * blockDim.x + threadIdx.x;
    if (i >= NK16 * 16 * 2 * 32) return;
    int lane = i & 31;
    int reg  = (i >> 5) & 1;
    int n8   = (i >> 6) & 15;
    int k16  = i >> 10;
    int n_g  = n8 * 8 + (lane >> 2);
    int k_g  = k16 * 16 + (lane & 3) * 2 + reg * 8;
    float w0 = W[n_g * IN_D + k_g];
    float w1 = W[n_g * IN_D + k_g + 1];
    __half2 hv(__float2half_rn(w0), __float2half_rn(w1));
    g_Wfrag[i] = *reinterpret_cast<uint32_t*>(&hv);
}

__global__ void prep_nodes_kernel(const float* __restrict__ nodes, int total4) {
    int i = blockIdx.x * blockDim.x + threadIdx.x;   // over float4 groups
    if (i >= total4) return;
    float4 v = reinterpret_cast<const float4*>(nodes)[i];
    __half h[4] = {__float2half_rn(v.x), __float2half_rn(v.y),
                   __float2half_rn(v.z), __float2half_rn(v.w)};
    *reinterpret_cast<uint2*>(g_Nf16 + i * 4) = *reinterpret_cast<uint2*>(h);
}

__global__ void __launch_bounds__(THREADS, 2)
edgeblock_mma_kernel(const float* __restrict__ edges,
                     const int* __restrict__ recv,
                     const int* __restrict__ send,
                     const float* __restrict__ bias,
                     float* __restrict__ out,
                     int E)
{
    extern __shared__ char smem[];
    const uint32_t sm = smem_u32(smem);
    const int t = threadIdx.x;
    const int lane = t & 31, wid = t >> 5;
    const int e0 = blockIdx.x * TM;

    const int m_base = (wid & 1) * 64;
    const int n8base = (wid >> 1) * 4;

    int* Ridx = (int*)(smem + RIDX_OFF);
    int* Sidx = (int*)(smem + SIDX_OFF);
    float* Bs = (float*)(smem + BIAS_OFF);
    if (t < TM) {
        int e = e0 + t;
        Ridx[t] = (e < E) ? recv[e] : 0;
        Sidx[t] = (e < E) ? send[e] : 0;
        Bs[t] = bias[t];
    }
    __syncthreads();

    // ---- staging ----
    auto stage = [&](int c, int b) {
        const uint32_t buf = sm + b * BUFSZ;
        const int coff = (c & 1) * KC;
        if (c < 2) {
#pragma unroll
            for (int i = 0; i < 8; ++i) {
                int idx = t + i * THREADS;
                int row = idx >> 4, s = idx & 15;
                uint32_t dst = buf + row * (S_F32 * 4) + s * 16;
                int e = e0 + row;
                const float* srcp = edges + (size_t)(e < E ? e : 0) * 128 + coff + s * 4;
                cp_async16(dst, srcp, (e < E) ? 16 : 0);
            }
        } else {
            const int* idxs = (c < 4) ? Ridx : Sidx;
#pragma unroll
            for (int i = 0; i < 4; ++i) {
                int idx = t + i * THREADS;
                int row = idx >> 3, p = idx & 7;
                int node = idxs[row];
                const char* srcp = (const char*)g_Nf16
                                 + ((size_t)node * 128 + coff) * 2 + p * 16;
                cp_async16(buf + row * STRB + p * 16, srcp, 16);
            }
        }
        CP_COMMIT();
    };

    float acc[4][4][4];
#pragma unroll
    for (int i = 0; i < 4; ++i)
#pragma unroll
        for (int j = 0; j < 4; ++j)
#pragma unroll
            for (int k = 0; k < 4; ++k) acc[i][j][k] = 0.f;

    const int gq = lane >> 2, t4 = lane & 3;
    const int lr = lane & 7, g4 = lane >> 3;
    const uint32_t abase_f32  = (uint32_t)(m_base + gq) * (S_F32 * 4) + (uint32_t)t4 * 8;
    const uint32_t abase_ldsm = (uint32_t)(m_base + lr + (g4 & 1) * 8) * STRB + (g4 >> 1) * 16;

    auto ldB = [&](int k16g, uint32_t (&bw)[4][2]) {
#pragma unroll
        for (int tn = 0; tn < 4; ++tn)
#pragma unroll
            for (int rg = 0; rg < 2; ++rg)
                bw[tn][rg] = __ldg(&g_Wfrag[(((k16g * 16) + n8base + tn) * 2 + rg) * 32 + lane]);
    };
    auto mma1 = [&](int tm, uint32_t (&a)[4], uint32_t (&bw)[4][2]) {
#pragma unroll
        for (int tn = 0; tn < 4; ++tn)
            mma16816(acc[tm][tn][0], acc[tm][tn][1], acc[tm][tn][2], acc[tm][tn][3],
                     a[0], a[1], a[2], a[3], bw[tn][0], bw[tn][1]);
    };

    // ---- compute: edge chunk (inline fp32 -> f16x2) ----
    auto compute_edge = [&](int c, int b) {
        const uint32_t bufb = sm + b * BUFSZ + abase_f32;
#pragma unroll
        for (int kk = 0; kk < 4; ++kk) {
            uint32_t bw[4][2];
            ldB(c * 4 + kk, bw);
#pragma unroll
            for (int tm = 0; tm < 4; ++tm) {
                uint32_t a[4];
#pragma unroll
                for (int rg = 0; rg < 4; ++rg) {
                    uint32_t addr = bufb + (uint32_t)(tm * 16 + (rg & 1) * 8) * (S_F32 * 4)
                                  + (uint32_t)(kk * 16 + (rg >> 1) * 8) * 4;
                    float2 f;
                    asm volatile("ld.shared.v2.f32 {%0,%1}, [%2];"
                                 : "=f"(f.x), "=f"(f.y) : "r"(addr));
                    a[rg] = f16x2(f.x, f.y);
                }
                mma1(tm, a, bw);
            }
        }
    };
    // ---- compute: node chunk (pure LDSM) ----
    auto compute_node = [&](int c, int b) {
        const uint32_t hb = sm + b * BUFSZ + abase_ldsm;
#pragma unroll
        for (int kk = 0; kk < 4; ++kk) {
            uint32_t bw[4][2];
            ldB(c * 4 + kk, bw);
#pragma unroll
            for (int tm = 0; tm < 4; ++tm) {
                uint32_t a[4];
                ldsm_x4(a[0], a[1], a[2], a[3], hb + tm * 16 * STRB + kk * 32);
                mma1(tm, a, bw);
            }
        }
    };

    // ---- 3-stage pipeline ----
    stage(0, 0);
    stage(1, 1);
#pragma unroll
    for (int c = 0; c < NCHUNK; ++c) {
        if (c < NCHUNK - 1) cp_wait<1>(); else cp_wait<0>();
        __syncthreads();
        if (c < 2) compute_edge(c, c % 3);
        else       compute_node(c, c % 3);
        if (c + 2 < NCHUNK) stage(c + 2, (c + 2) % 3);
    }

    // ---- epilogue ----
#pragma unroll
    for (int tm = 0; tm < 4; ++tm) {
        int r0 = e0 + m_base + tm * 16 + gq;
        int r1 = r0 + 8;
#pragma unroll
        for (int tn = 0; tn < 4; ++tn) {
            int cbase = n8base * 8 + tn * 8 + t4 * 2;
            float b0 = Bs[cbase], b1 = Bs[cbase + 1];
            if (r0 < E) {
                float2 v = make_float2(acc[tm][tn][0] + b0, acc[tm][tn][1] + b1);
                *reinterpret_cast<float2*>(out + (size_t)r0 * OUT_D + cbase) = v;
            }
            if (r1 < E) {
                float2 v = make_float2(acc[tm][tn][2] + b0, acc[tm][tn][3] + b1);
                *reinterpret_cast<float2*>(out + (size_t)r1 * OUT_D + cbase) = v;
            }
        }
    }
}

extern "C" void kernel_launch(void* const* d_in, const int* in_sizes, int n_in,
                              void* d_out, int out_size)
{
    const float* nodes = (const float*)d_in[0];
    const float* edges = (const float*)d_in[1];
    const int*   recv  = (const int*)d_in[2];
    const int*   send  = (const int*)d_in[3];
    const float* W     = (const float*)d_in[4];
    const float* bias  = (const float*)d_in[5];
    float*       out   = (float*)d_out;
    int E = in_sizes[2];
    int n_node_f = in_sizes[0];              // N_NODES * 128

    cudaFuncSetAttribute(edgeblock_mma_kernel,
                         cudaFuncAttributeMaxDynamicSharedMemorySize, SM_TOTAL);

    prep_W_kernel<<<(NK16 * 16 * 2 * 32 + 255) / 256, 256>>>(W);
    int total4 = n_node_f / 4;
    prep_nodes_kernel<<<(total4 + 255) / 256, 256>>>(nodes, total4);
    int grid = (E + TM - 1) / TM;
    edgeblock_mma_kernel<<<grid, THREADS, SM_TOTAL>>>(edges, recv, send, bias, out, E);
}

// round 13
// speedup vs baseline: 2.6516x; 1.0007x over previous
#include <cuda_runtime.h>
#include <cuda_fp16.h>
#include <cstdint>

// EdgeBlock: out[e,:] = W @ concat(edges[e], nodes[recv[e]], nodes[send[e]]) + b
// E=500000, NODE_D=EDGE_D=128, IN_D=384, W [128,384] row-major, out [E,128] f32.
// R12: single-pass fp16 mma m16n8k16 (X and W both fp16, fp32 accum).
//      Measured-anchor error model: R11 (X-only trunc) = 2.08e-4; adding W
//      trunc in quadrature -> ~2.9e-4 << 1e-3.

#define IN_D    384
#define OUT_D   128
#define TM      128
#define KC      64
#define NCHUNK  6
#define NK16    24
#define THREADS 256
#define N_NODES_MAX 50000

#define S_F32   68                   // f32 row stride for edge buffers (272 B)
#define STRB    144                  // fp16 row stride for node buffers (bytes)
#define BUFSZ   36864                // per-stage buffer (fits both formats)
#define RIDX_OFF (3 * BUFSZ)         // 110592
#define SIDX_OFF (RIDX_OFF + 512)
#define BIAS_OFF (SIDX_OFF + 512)
#define SM_TOTAL (BIAS_OFF + 512)    // 112128

__device__ __forceinline__ uint32_t smem_u32(const void* p) {
    uint32_t a;
    asm("{ .reg .u64 t; cvta.to.shared.u64 t, %1; cvt.u32.u64 %0, t; }" : "=r"(a) : "l"(p));
    return a;
}
__device__ __forceinline__ void cp_async16(uint32_t dst, const void* src, int srcsz) {
    asm volatile("cp.async.cg.shared.global [%0], [%1], 16, %2;"
                 :: "r"(dst), "l"(src), "r"(srcsz) : "memory");
}
#define CP_COMMIT() asm volatile("cp.async.commit_group;" ::: "memory")
template <int N>
__device__ __forceinline__ void cp_wait() {
    asm volatile("cp.async.wait_group %0;" :: "n"(N) : "memory");
}
__device__ __forceinline__ void ldsm_x4(uint32_t& r0, uint32_t& r1, uint32_t& r2, uint32_t& r3,
                                        uint32_t addr) {
    asm volatile("ldmatrix.sync.aligned.m8n8.x4.shared.b16 {%0,%1,%2,%3}, [%4];"
                 : "=r"(r0), "=r"(r1), "=r"(r2), "=r"(r3) : "r"(addr));
}
__device__ __forceinline__ void mma16816(float& c0, float& c1, float& c2, float& c3,
                                         uint32_t a0, uint32_t a1, uint32_t a2, uint32_t a3,
                                         uint32_t b0, uint32_t b1) {
    asm volatile("mma.sync.aligned.m16n8k16.row.col.f32.f16.f16.f32 "
                 "{%0,%1,%2,%3}, {%4,%5,%6,%7}, {%8,%9}, {%0,%1,%2,%3};"
                 : "+f"(c0), "+f"(c1), "+f"(c2), "+f"(c3)
                 : "r"(a0), "r"(a1), "r"(a2), "r"(a3), "r"(b0), "r"(b1));
}
__device__ __forceinline__ uint32_t f16x2(float x, float y) {
    uint32_t r;
    asm("cvt.rn.f16x2.f32 %0, %1, %2;" : "=r"(r) : "f"(y), "f"(x));
    return r;
}

// ---- W pre-packed as mma B-fragments: [k16][n8][reg][lane] -> uint32 f16x2 ----
__device__ __align__(16) uint32_t g_Wfrag[NK16 * 16 * 2 * 32];
// ---- nodes pre-converted to fp16, [node][128] row-major ----
__device__ __align__(16) __half g_Nf16[(size_t)N_NODES_MAX * 128];

__global__ void prep_W_kernel(const float* __restrict__ W) {
    int i = blockIdx.x * blockDim.x + threadIdx.x;
    if (i >= NK16 * 16 * 2 * 32) return;
    int lane = i & 31;
    int reg  = (i >> 5) & 1;
    int n8   = (i >> 6) & 15;
    int k16  = i >> 10;
    int n_g  = n8 * 8 + (lane >> 2);
    int k_g  = k16 * 16 + (lane & 3) * 2 + reg * 8;
    float w0 = W[n_g * IN_D + k_g];
    float w1 = W[n_g * IN_D + k_g + 1];
    __half2 hv(__float2half_rn(w0), __float2half_rn(w1));
    g_Wfrag[i] = *reinterpret_cast<uint32_t*>(&hv);
}

__global__ void prep_nodes_kernel(const float* __restrict__ nodes, int total4) {
    int i = blockIdx.x * blockDim.x + threadIdx.x;   // over float4 groups
    if (i >= total4) return;
    float4 v = reinterpret_cast<const float4*>(nodes)[i];
    __half h[4] = {__float2half_rn(v.x), __float2half_rn(v.y),
                   __float2half_rn(v.z), __float2half_rn(v.w)};
    *reinterpret_cast<uint2*>(g_Nf16 + i * 4) = *reinterpret_cast<uint2*>(h);
}

__global__ void __launch_bounds__(THREADS, 2)
edgeblock_mma_kernel(const float* __restrict__ edges,
                     const int* __restrict__ recv,
                     const int* __restrict__ send,
                     const float* __restrict__ bias,
                     float* __restrict__ out,
                     int E)
{
    extern __shared__ char smem[];
    const uint32_t sm = smem_u32(smem);
    const int t = threadIdx.x;
    const int lane = t & 31, wid = t >> 5;
    const int e0 = blockIdx.x * TM;

    const int m_base = (wid & 1) * 64;
    const int n8base = (wid >> 1) * 4;

    int* Ridx = (int*)(smem + RIDX_OFF);
    int* Sidx = (int*)(smem + SIDX_OFF);
    float* Bs = (float*)(smem + BIAS_OFF);
    if (t < TM) {
        int e = e0 + t;
        Ridx[t] = (e < E) ? recv[e] : 0;
        Sidx[t] = (e < E) ? send[e] : 0;
        Bs[t] = bias[t];
    }
    __syncthreads();

    // ---- staging ----
    auto stage = [&](int c, int b) {
        const uint32_t buf = sm + b * BUFSZ;
        const int coff = (c & 1) * KC;
        if (c < 2) {
#pragma unroll
            for (int i = 0; i < 8; ++i) {
                int idx = t + i * THREADS;
                int row = idx >> 4, s = idx & 15;
                uint32_t dst = buf + row * (S_F32 * 4) + s * 16;
                int e = e0 + row;
                const float* srcp = edges + (size_t)(e < E ? e : 0) * 128 + coff + s * 4;
                cp_async16(dst, srcp, (e < E) ? 16 : 0);
            }
        } else {
            const int* idxs = (c < 4) ? Ridx : Sidx;
#pragma unroll
            for (int i = 0; i < 4; ++i) {
                int idx = t + i * THREADS;
                int row = idx >> 3, p = idx & 7;
                int node = idxs[row];
                const char* srcp = (const char*)g_Nf16
                                 + ((size_t)node * 128 + coff) * 2 + p * 16;
                cp_async16(buf + row * STRB + p * 16, srcp, 16);
            }
        }
        CP_COMMIT();
    };

    float acc[4][4][4];
#pragma unroll
    for (int i = 0; i < 4; ++i)
#pragma unroll
        for (int j = 0; j < 4; ++j)
#pragma unroll
            for (int k = 0; k < 4; ++k) acc[i][j][k] = 0.f;

    const int gq = lane >> 2, t4 = lane & 3;
    const int lr = lane & 7, g4 = lane >> 3;
    const uint32_t abase_f32  = (uint32_t)(m_base + gq) * (S_F32 * 4) + (uint32_t)t4 * 8;
    const uint32_t abase_ldsm = (uint32_t)(m_base + lr + (g4 & 1) * 8) * STRB + (g4 >> 1) * 16;

    auto ldB = [&](int k16g, uint32_t (&bw)[4][2]) {
#pragma unroll
        for (int tn = 0; tn < 4; ++tn)
#pragma unroll
            for (int rg = 0; rg < 2; ++rg)
                bw[tn][rg] = __ldg(&g_Wfrag[(((k16g * 16) + n8base + tn) * 2 + rg) * 32 + lane]);
    };
    auto mma1 = [&](int tm, uint32_t (&a)[4], uint32_t (&bw)[4][2]) {
#pragma unroll
        for (int tn = 0; tn < 4; ++tn)
            mma16816(acc[tm][tn][0], acc[tm][tn][1], acc[tm][tn][2], acc[tm][tn][3],
                     a[0], a[1], a[2], a[3], bw[tn][0], bw[tn][1]);
    };

    // ---- compute: edge chunk (inline fp32 -> f16x2) ----
    auto compute_edge = [&](int c, int b) {
        const uint32_t bufb = sm + b * BUFSZ + abase_f32;
#pragma unroll
        for (int kk = 0; kk < 4; ++kk) {
            uint32_t bw[4][2];
            ldB(c * 4 + kk, bw);
#pragma unroll
            for (int tm = 0; tm < 4; ++tm) {
                uint32_t a[4];
#pragma unroll
                for (int rg = 0; rg < 4; ++rg) {
                    uint32_t addr = bufb + (uint32_t)(tm * 16 + (rg & 1) * 8) * (S_F32 * 4)
                                  + (uint32_t)(kk * 16 + (rg >> 1) * 8) * 4;
                    float2 f;
                    asm volatile("ld.shared.v2.f32 {%0,%1}, [%2];"
                                 : "=f"(f.x), "=f"(f.y) : "r"(addr));
                    a[rg] = f16x2(f.x, f.y);
                }
                mma1(tm, a, bw);
            }
        }
    };
    // ---- compute: node chunk (pure LDSM) ----
    auto compute_node = [&](int c, int b) {
        const uint32_t hb = sm + b * BUFSZ + abase_ldsm;
#pragma unroll
        for (int kk = 0; kk < 4; ++kk) {
            uint32_t bw[4][2];
            ldB(c * 4 + kk, bw);
#pragma unroll
            for (int tm = 0; tm < 4; ++tm) {
                uint32_t a[4];
                ldsm_x4(a[0], a[1], a[2], a[3], hb + tm * 16 * STRB + kk * 32);
                mma1(tm, a, bw);
            }
        }
    };

    // ---- 3-stage pipeline ----
    stage(0, 0);
    stage(1, 1);
#pragma unroll
    for (int c = 0; c < NCHUNK; ++c) {
        if (c < NCHUNK - 1) cp_wait<1>(); else cp_wait<0>();
        __syncthreads();
        if (c < 2) compute_edge(c, c % 3);
        else       compute_node(c, c % 3);
        if (c + 2 < NCHUNK) stage(c + 2, (c + 2) % 3);
    }

    // ---- epilogue ----
#pragma unroll
    for (int tm = 0; tm < 4; ++tm) {
        int r0 = e0 + m_base + tm * 16 + gq;
        int r1 = r0 + 8;
#pragma unroll
        for (int tn = 0; tn < 4; ++tn) {
            int cbase = n8base * 8 + tn * 8 + t4 * 2;
            float b0 = Bs[cbase], b1 = Bs[cbase + 1];
            if (r0 < E) {
                float2 v = make_float2(acc[tm][tn][0] + b0, acc[tm][tn][1] + b1);
                *reinterpret_cast<float2*>(out + (size_t)r0 * OUT_D + cbase) = v;
            }
            if (r1 < E) {
                float2 v = make_float2(acc[tm][tn][2] + b0, acc[tm][tn][3] + b1);
                *reinterpret_cast<float2*>(out + (size_t)r1 * OUT_D + cbase) = v;
            }
        }
    }
}

extern "C" void kernel_launch(void* const* d_in, const int* in_sizes, int n_in,
                              void* d_out, int out_size)
{
    const float* nodes = (const float*)d_in[0];
    const float* edges = (const float*)d_in[1];
    const int*   recv  = (const int*)d_in[2];
    const int*   send  = (const int*)d_in[3];
    const float* W     = (const float*)d_in[4];
    const float* bias  = (const float*)d_in[5];
    float*       out   = (float*)d_out;
    int E = in_sizes[2];
    int n_node_f = in_sizes[0];              // N_NODES * 128

    cudaFuncSetAttribute(edgeblock_mma_kernel,
                         cudaFuncAttributeMaxDynamicSharedMemorySize, SM_TOTAL);

    prep_W_kernel<<<(NK16 * 16 * 2 * 32 + 255) / 256, 256>>>(W);
    int total4 = n_node_f / 4;
    prep_nodes_kernel<<<(total4 + 255) / 256, 256>>>(nodes, total4);
    int grid = (E + TM - 1) / TM;
    edgeblock_mma_kernel<<<grid, THREADS, SM_TOTAL>>>(edges, recv, send, bias, out, E);
}